// round 9
// baseline (speedup 1.0000x reference)
#include <cuda_runtime.h>
#include <cuda_bf16.h>
#include <cstdint>

// Problem constants
#define BB 64
#define TT 128
#define DD 512
#define HH 30
#define TM 98
static constexpr float INV_TEMP = 1.0f / 0.07f;

// Scratch (device globals: no allocation allowed)
__device__ __align__(16) __nv_bfloat16 g_zbf[BB * TT * DD];    // bf16 z_seq
__device__ __align__(16) __nv_bfloat16 g_cbf[BB * TT * DD];    // bf16 c_seq
__device__ __align__(16) __nv_bfloat16 g_cproj[BB * TT * DD];  // bf16 c_proj
__device__ __align__(16) __nv_bfloat16 g_Wt[DD * DD];          // bf16 W^T ([n][p])
__device__ float g_partials[TM * HH];

// ---------------------------------------------------------------------------
// PTX helpers
// ---------------------------------------------------------------------------
__device__ __forceinline__ uint32_t smem_u32(const void* p) {
    return (uint32_t)__cvta_generic_to_shared(p);
}
__device__ __forceinline__ void ldm_x4(uint32_t& a0, uint32_t& a1, uint32_t& a2,
                                       uint32_t& a3, uint32_t addr) {
    asm volatile("ldmatrix.sync.aligned.m8n8.x4.shared.b16 {%0,%1,%2,%3}, [%4];\n"
                 : "=r"(a0), "=r"(a1), "=r"(a2), "=r"(a3) : "r"(addr));
}
__device__ __forceinline__ void mma_bf16(float* c, uint32_t a0, uint32_t a1,
                                         uint32_t a2, uint32_t a3,
                                         uint32_t b0, uint32_t b1) {
    asm volatile(
        "mma.sync.aligned.m16n8k16.row.col.f32.bf16.bf16.f32 "
        "{%0,%1,%2,%3}, {%4,%5,%6,%7}, {%8,%9}, {%0,%1,%2,%3};\n"
        : "+f"(c[0]), "+f"(c[1]), "+f"(c[2]), "+f"(c[3])
        : "r"(a0), "r"(a1), "r"(a2), "r"(a3), "r"(b0), "r"(b1));
}
__device__ __forceinline__ void cp_async16(uint32_t dst, const void* src) {
    asm volatile("cp.async.ca.shared.global [%0], [%1], 16;\n" :: "r"(dst), "l"(src));
}
__device__ __forceinline__ void cp_commit() {
    asm volatile("cp.async.commit_group;\n");
}
template <int N>
__device__ __forceinline__ void cp_wait() {
    asm volatile("cp.async.wait_group %0;\n" :: "n"(N));
}

// ---------------------------------------------------------------------------
// Convert fp32 -> bf16 (vectorized)
// ---------------------------------------------------------------------------
__global__ void k_convert(const float* __restrict__ src, __nv_bfloat16* __restrict__ dst) {
    int i = blockIdx.x * blockDim.x + threadIdx.x;
    int idx = i * 4;
    if (idx < BB * TT * DD) {
        float4 v = *(const float4*)(src + idx);
        *(__nv_bfloat162*)(dst + idx) = __floats2bfloat162_rn(v.x, v.y);
        *(__nv_bfloat162*)(dst + idx + 2) = __floats2bfloat162_rn(v.z, v.w);
    }
}

// Transpose+convert W fp32 [p][n] -> bf16 g_Wt [n][p]
__global__ void k_convert_w(const float* __restrict__ W) {
    int i = blockIdx.x * blockDim.x + threadIdx.x;
    if (i < DD * DD) {
        int n = i >> 9;
        int p = i & 511;
        g_Wt[i] = __float2bfloat16(W[p * DD + n]);
    }
}

// ---------------------------------------------------------------------------
// GEMM1: c_proj = c @ W + b.  M=8192, N=512, K=512.
// CTA tile 128x256, 512 thr (16 warps, warp tile 32x64), K-chunk 64,
// cp.async 2-stage. Grid (64,2) = 128 CTAs = 1 wave.
// ---------------------------------------------------------------------------
#define G1_LD 72
#define G1_A_B (128 * G1_LD * 2)        // 18432
#define G1_B_B (256 * G1_LD * 2)        // 36864
#define G1_STAGE (G1_A_B + G1_B_B)      // 55296
#define G1_SMEM (2 * G1_STAGE)          // 110592

__global__ __launch_bounds__(512) void k_gemm1(const float* __restrict__ bias) {
    extern __shared__ char sm[];
    const int tid = threadIdx.x;
    const int w = tid >> 5;
    const int lane = tid & 31;
    const int wr = w >> 2;          // 0..3 : rows wr*32
    const int wc = w & 3;           // 0..3 : cols wc*64
    const int g = lane >> 2;
    const int t4 = lane & 3;
    const int m0 = blockIdx.x * 128;
    const int n0 = blockIdx.y * 256;

    float acc[2][8][4];
#pragma unroll
    for (int a = 0; a < 2; a++)
#pragma unroll
        for (int nt = 0; nt < 8; nt++)
#pragma unroll
            for (int e = 0; e < 4; e++) acc[a][nt][e] = 0.f;

    auto issue = [&](int kc, int st) {
        char* base = sm + st * G1_STAGE;
        uint32_t sa = smem_u32(base);
        uint32_t sb = sa + G1_A_B;
#pragma unroll
        for (int it = 0; it < 2; it++) {
            int idx = tid + it * 512;          // 0..1023: 128 rows x 8 u4
            int r = idx >> 3, cu = idx & 7;
            cp_async16(sa + (r * G1_LD + cu * 8) * 2,
                       g_cbf + (size_t)(m0 + r) * DD + kc * 64 + cu * 8);
        }
#pragma unroll
        for (int it = 0; it < 4; it++) {
            int idx = tid + it * 512;          // 0..2047: 256 rows x 8 u4
            int r = idx >> 3, cu = idx & 7;
            cp_async16(sb + (r * G1_LD + cu * 8) * 2,
                       g_Wt + (size_t)(n0 + r) * DD + kc * 64 + cu * 8);
        }
        cp_commit();
    };

    issue(0, 0);

    for (int kc = 0; kc < 8; kc++) {
        if (kc < 7) issue(kc + 1, (kc + 1) & 1);
        if (kc < 7) cp_wait<1>(); else cp_wait<0>();
        __syncthreads();
        char* base = sm + (kc & 1) * G1_STAGE;
        uint32_t sa = smem_u32(base);
        uint32_t sb = sa + G1_A_B;
#pragma unroll
        for (int ks = 0; ks < 4; ks++) {
            uint32_t af[2][4];
#pragma unroll
            for (int a = 0; a < 2; a++) {
                uint32_t addr = sa + ((wr * 32 + a * 16 + (lane & 15)) * G1_LD +
                                      ks * 16 + (lane >> 4) * 8) * 2;
                ldm_x4(af[a][0], af[a][1], af[a][2], af[a][3], addr);
            }
#pragma unroll
            for (int np = 0; np < 4; np++) {
                uint32_t b0, b1, b2, b3;
                uint32_t addr = sb + ((wc * 64 + np * 16 + ((lane >> 4) & 1) * 8 +
                                       (lane & 7)) * G1_LD +
                                      ks * 16 + ((lane >> 3) & 1) * 8) * 2;
                ldm_x4(b0, b1, b2, b3, addr);
#pragma unroll
                for (int a = 0; a < 2; a++) {
                    mma_bf16(acc[a][2 * np], af[a][0], af[a][1], af[a][2], af[a][3], b0, b1);
                    mma_bf16(acc[a][2 * np + 1], af[a][0], af[a][1], af[a][2], af[a][3], b2, b3);
                }
            }
        }
        __syncthreads();
    }

    // Epilogue: bias + bf16 store
#pragma unroll
    for (int a = 0; a < 2; a++) {
        int r0 = m0 + wr * 32 + a * 16 + g;
#pragma unroll
        for (int nt = 0; nt < 8; nt++) {
            int col = n0 + wc * 64 + nt * 8 + t4 * 2;
            float bv0 = bias[col], bv1 = bias[col + 1];
            *(__nv_bfloat162*)(g_cproj + (size_t)r0 * DD + col) =
                __floats2bfloat162_rn(acc[a][nt][0] + bv0, acc[a][nt][1] + bv1);
            *(__nv_bfloat162*)(g_cproj + (size_t)(r0 + 8) * DD + col) =
                __floats2bfloat162_rn(acc[a][nt][2] + bv0, acc[a][nt][3] + bv1);
        }
    }
}

// ---------------------------------------------------------------------------
// Fused scores + LSE - diag, diagonal-block version, 512 threads.
// Grid (49, 3): CTA = (t-pair {t0,t0+1}, s-window). 16 warps.
// C pair resident (M=128 x K=512, ld 520). Phase = 4 s-slots x 4 warps
// (warp tile 32x64 over M=128). Z streamed in 64-col K-chunks,
// double-buffered (2 stages x 4 slots, ld 72). Epilogue masks k outside [1,30].
// s-window: y=0 -> 11 s's, y=1/2 -> 10. Phases of 4 slots (last partial).
// ---------------------------------------------------------------------------
#define SC_LD 520
#define SC_BYTES (128 * SC_LD * 2)       // 133120
#define SZ_LD 72
#define SZ_SLOT (64 * SZ_LD * 2)         // 9216
#define SZ_BYTES (8 * SZ_SLOT)           // 73728
#define S_SMEM (SC_BYTES + SZ_BYTES + 64)  // 206912

__global__ __launch_bounds__(512) void k_scores() {
    extern __shared__ char sm[];
    uint32_t sC = smem_u32(sm);
    uint32_t sZ0 = sC + SC_BYTES;
    float* sRed = (float*)(sm + SC_BYTES + SZ_BYTES);

    const int t0 = blockIdx.x * 2;
    const int y = blockIdx.y;
    const int s_base = t0 + 1 + ((y == 0) ? 0 : (y == 1) ? 11 : 21);
    const int win = (y == 0) ? 11 : 10;
    const int P = (win + 3) >> 2;       // 3 phases (4,4,3) or (4,4,2)
    const int ITERS = 8 * P;            // 8 K-chunks of 64 per phase

    const int tid = threadIdx.x;
    const int w = tid >> 5;
    const int lane = tid & 31;
    const int slot = w >> 2;            // s-slot within phase (0..3)
    const int wr = w & 3;               // row quarter: rows wr*32..+32 of M=128
    const int g = lane >> 2;
    const int t4 = lane & 3;

    // --- Prologue: C tiles for t0 and t0+1 (rows 0-63 / 64-127) ---
#pragma unroll
    for (int it = 0; it < 16; it++) {
        int idx = tid + it * 512;           // 0..8191 -> 128 rows x 64 uint4
        int r = idx >> 6, cu = idx & 63;
        int i = r & 63, tt = t0 + (r >> 6);
        cp_async16(sC + (r * SC_LD + cu * 8) * 2,
                   g_cproj + ((size_t)i * TT + tt) * DD + cu * 8);
    }
    cp_commit();

    auto issue_z = [&](int it) {
        int p = it >> 3, ch = it & 7, st = it & 1;
        int nsl = win - p * 4; if (nsl > 4) nsl = 4;
        int r = tid >> 3, cu = tid & 7;     // 512 thr = 64 rows x 8 u4 per slot
        for (int sl = 0; sl < nsl; sl++) {
            int s = s_base + p * 4 + sl;
            uint32_t dst = sZ0 + (uint32_t)(st * 4 + sl) * SZ_SLOT;
            cp_async16(dst + (r * SZ_LD + cu * 8) * 2,
                       g_zbf + ((size_t)r * TT + s) * DD + ch * 64 + cu * 8);
        }
        cp_commit();
    };

    issue_z(0);
    issue_z(1);
    cp_wait<1>();       // C + stage0 ready
    __syncthreads();

    float acc[2][8][4];
#pragma unroll
    for (int a = 0; a < 2; a++)
#pragma unroll
        for (int nt = 0; nt < 8; nt++)
#pragma unroll
            for (int e = 0; e < 4; e++) acc[a][nt][e] = 0.f;

    for (int it = 0; it < ITERS; it++) {
        const int p = it >> 3, ch = it & 7;
        const bool slot_active = (p * 4 + slot) < win;

        // --- Compute this 64-col K-chunk ---
        if (slot_active) {
            uint32_t sz = sZ0 + (uint32_t)((it & 1) * 4 + slot) * SZ_SLOT;
#pragma unroll
            for (int ks = 0; ks < 4; ks++) {
                uint32_t af[2][4];
#pragma unroll
                for (int a = 0; a < 2; a++) {
                    uint32_t addr = sC + ((wr * 32 + a * 16 + (lane & 15)) * SC_LD +
                                          ch * 64 + ks * 16 + (lane >> 4) * 8) * 2;
                    ldm_x4(af[a][0], af[a][1], af[a][2], af[a][3], addr);
                }
#pragma unroll
                for (int np = 0; np < 4; np++) {
                    uint32_t b0, b1, b2, b3;
                    uint32_t addr = sz + ((np * 16 + ((lane >> 4) & 1) * 8 +
                                           (lane & 7)) * SZ_LD +
                                          ks * 16 + ((lane >> 3) & 1) * 8) * 2;
                    ldm_x4(b0, b1, b2, b3, addr);
#pragma unroll
                    for (int a = 0; a < 2; a++) {
                        mma_bf16(acc[a][2 * np], af[a][0], af[a][1], af[a][2], af[a][3], b0, b1);
                        mma_bf16(acc[a][2 * np + 1], af[a][0], af[a][1], af[a][2], af[a][3], b2, b3);
                    }
                }
            }
        }
        __syncthreads();                    // stage fully consumed

        if (it + 2 < ITERS) issue_z(it + 2);

        // --- End of phase: LSE - diag epilogue ---
        if (ch == 7) {
            const int s = s_base + p * 4 + slot;
            const int th = wr >> 1;         // 0 -> t0 rows, 1 -> t0+1 rows
            const int k = s - (t0 + th);
            const bool valid = slot_active && (k >= 1) && (k <= 30);

            float local = 0.f;
            if (valid) {
#pragma unroll
                for (int a = 0; a < 2; a++) {
#pragma unroll
                    for (int rp = 0; rp < 2; rp++) {
                        const int e0 = rp * 2;
                        float m = -3.4e38f;
#pragma unroll
                        for (int nt = 0; nt < 8; nt++)
                            m = fmaxf(m, fmaxf(acc[a][nt][e0], acc[a][nt][e0 + 1]));
                        m = fmaxf(m, __shfl_xor_sync(0xffffffffu, m, 1));
                        m = fmaxf(m, __shfl_xor_sync(0xffffffffu, m, 2));
                        float se = 0.f;
#pragma unroll
                        for (int nt = 0; nt < 8; nt++) {
                            se += expf((acc[a][nt][e0] - m) * INV_TEMP);
                            se += expf((acc[a][nt][e0 + 1] - m) * INV_TEMP);
                        }
                        se += __shfl_xor_sync(0xffffffffu, se, 1);
                        se += __shfl_xor_sync(0xffffffffu, se, 2);
                        float lse = m * INV_TEMP + logf(se);
                        int r = wr * 32 + a * 16 + rp * 8 + g;   // 0..127
                        int j = r & 63;                          // diag col
                        if (t4 == ((j >> 1) & 3))
                            local += lse - acc[a][j >> 3][e0 + (j & 1)] * INV_TEMP;
                    }
                }
            }
#pragma unroll
            for (int off = 16; off > 0; off >>= 1)
                local += __shfl_xor_sync(0xffffffffu, local, off);
            if (lane == 0) sRed[w] = local;
            __syncthreads();
            // sRed[w]: w = slot*4 + (half*2 + {0,1})
            if (tid < 8) {
                int wsl = tid >> 1, half = tid & 1;
                if (p * 4 + wsl < win) {
                    int ss = s_base + p * 4 + wsl;
                    int tt = t0 + half;
                    int kk = ss - tt;
                    if (kk >= 1 && kk <= 30)
                        g_partials[tt * HH + kk - 1] =
                            sRed[wsl * 4 + half * 2] + sRed[wsl * 4 + half * 2 + 1];
                }
            }
            // zero accumulators for next phase
#pragma unroll
            for (int a = 0; a < 2; a++)
#pragma unroll
                for (int nt = 0; nt < 8; nt++)
#pragma unroll
                    for (int e = 0; e < 4; e++) acc[a][nt][e] = 0.f;
        }

        if (it + 1 < ITERS) {
            if (it + 2 < ITERS) cp_wait<1>(); else cp_wait<0>();
            __syncthreads();                // next stage ready
        }
    }
}

// ---------------------------------------------------------------------------
// Final deterministic reduction
// ---------------------------------------------------------------------------
__global__ void k_reduce(float* __restrict__ out) {
    __shared__ float sh[256];
    int tid = threadIdx.x;
    float ssum = 0.f;
    for (int i = tid; i < TM * HH; i += 256) ssum += g_partials[i];
    sh[tid] = ssum;
    __syncthreads();
    for (int off = 128; off > 0; off >>= 1) {
        if (tid < off) sh[tid] += sh[tid + off];
        __syncthreads();
    }
    if (tid == 0) out[0] = sh[0] / (float)(TM * HH * BB);
}

// ---------------------------------------------------------------------------
extern "C" void kernel_launch(void* const* d_in, const int* in_sizes, int n_in,
                              void* d_out, int out_size) {
    const float* z = (const float*)d_in[0];
    const float* c = (const float*)d_in[1];
    const float* W = (const float*)d_in[2];
    const float* bias = (const float*)d_in[3];
    float* out = (float*)d_out;
    (void)in_sizes; (void)n_in; (void)out_size;

    cudaFuncSetAttribute(k_scores, cudaFuncAttributeMaxDynamicSharedMemorySize, S_SMEM);
    cudaFuncSetAttribute(k_gemm1, cudaFuncAttributeMaxDynamicSharedMemorySize, G1_SMEM);

    __nv_bfloat16* zb = nullptr;
    __nv_bfloat16* cb = nullptr;
    cudaGetSymbolAddress((void**)&zb, g_zbf);
    cudaGetSymbolAddress((void**)&cb, g_cbf);

    k_convert<<<4096, 256>>>(z, zb);
    k_convert<<<4096, 256>>>(c, cb);
    k_convert_w<<<(DD * DD + 511) / 512, 512>>>(W);
    k_gemm1<<<dim3(64, 2), 512, G1_SMEM>>>(bias);
    k_scores<<<dim3(49, 3), 512, S_SMEM>>>();
    k_reduce<<<1, 256>>>(out);
}

// round 11
// speedup vs baseline: 1.0303x; 1.0303x over previous
#include <cuda_runtime.h>
#include <cuda_bf16.h>
#include <cstdint>

// Problem constants
#define BB 64
#define TT 128
#define DD 512
#define HH 30
#define TM 98
static constexpr float INV_TEMP = 1.0f / 0.07f;

// Scratch (device globals: no allocation allowed)
__device__ __align__(16) __nv_bfloat16 g_zbf[BB * TT * DD];    // bf16 z_seq
__device__ __align__(16) __nv_bfloat16 g_cbf[BB * TT * DD];    // bf16 c_seq
__device__ __align__(16) __nv_bfloat16 g_cproj[BB * TT * DD];  // bf16 c_proj
__device__ __align__(16) __nv_bfloat16 g_Wt[DD * DD];          // bf16 W^T ([n][p])
__device__ float g_partials[TM * HH];

// ---------------------------------------------------------------------------
// PTX helpers
// ---------------------------------------------------------------------------
__device__ __forceinline__ uint32_t smem_u32(const void* p) {
    return (uint32_t)__cvta_generic_to_shared(p);
}
__device__ __forceinline__ void ldm_x4(uint32_t& a0, uint32_t& a1, uint32_t& a2,
                                       uint32_t& a3, uint32_t addr) {
    asm volatile("ldmatrix.sync.aligned.m8n8.x4.shared.b16 {%0,%1,%2,%3}, [%4];\n"
                 : "=r"(a0), "=r"(a1), "=r"(a2), "=r"(a3) : "r"(addr));
}
__device__ __forceinline__ void mma_bf16(float* c, uint32_t a0, uint32_t a1,
                                         uint32_t a2, uint32_t a3,
                                         uint32_t b0, uint32_t b1) {
    asm volatile(
        "mma.sync.aligned.m16n8k16.row.col.f32.bf16.bf16.f32 "
        "{%0,%1,%2,%3}, {%4,%5,%6,%7}, {%8,%9}, {%0,%1,%2,%3};\n"
        : "+f"(c[0]), "+f"(c[1]), "+f"(c[2]), "+f"(c[3])
        : "r"(a0), "r"(a1), "r"(a2), "r"(a3), "r"(b0), "r"(b1));
}
__device__ __forceinline__ void cp_async16(uint32_t dst, const void* src) {
    asm volatile("cp.async.ca.shared.global [%0], [%1], 16;\n" :: "r"(dst), "l"(src));
}
__device__ __forceinline__ void cp_commit() {
    asm volatile("cp.async.commit_group;\n");
}
template <int N>
__device__ __forceinline__ void cp_wait() {
    asm volatile("cp.async.wait_group %0;\n" :: "n"(N));
}

// ---------------------------------------------------------------------------
// Convert fp32 -> bf16 (vectorized)
// ---------------------------------------------------------------------------
__global__ void k_convert(const float* __restrict__ src, __nv_bfloat16* __restrict__ dst) {
    int i = blockIdx.x * blockDim.x + threadIdx.x;
    int idx = i * 4;
    if (idx < BB * TT * DD) {
        float4 v = *(const float4*)(src + idx);
        *(__nv_bfloat162*)(dst + idx) = __floats2bfloat162_rn(v.x, v.y);
        *(__nv_bfloat162*)(dst + idx + 2) = __floats2bfloat162_rn(v.z, v.w);
    }
}

// Transpose+convert W fp32 [p][n] -> bf16 g_Wt [n][p]
__global__ void k_convert_w(const float* __restrict__ W) {
    int i = blockIdx.x * blockDim.x + threadIdx.x;
    if (i < DD * DD) {
        int n = i >> 9;
        int p = i & 511;
        g_Wt[i] = __float2bfloat16(W[p * DD + n]);
    }
}

// ---------------------------------------------------------------------------
// GEMM1: c_proj = c @ W + b.  M=8192, N=512, K=512.
// CTA tile 128x128, 256 thr (8 warps, warp tile 32x64), K-chunk 64,
// cp.async 3-stage (loads 2 chunks ahead).
// ---------------------------------------------------------------------------
#define G1_LD 72
#define G1_TILE_B (128 * G1_LD * 2)      // 18432
#define G1_STAGE_B (2 * G1_TILE_B)      // 36864
#define G1_SMEM (3 * G1_STAGE_B)        // 110592

__global__ __launch_bounds__(256) void k_gemm1(const float* __restrict__ bias) {
    extern __shared__ char sm[];
    const int tid = threadIdx.x;
    const int w = tid >> 5;
    const int lane = tid & 31;
    const int wr = w >> 1;
    const int wc = w & 1;
    const int g = lane >> 2;
    const int t4 = lane & 3;
    const int m0 = blockIdx.x * 128;
    const int n0 = blockIdx.y * 128;

    float acc[2][8][4];
#pragma unroll
    for (int a = 0; a < 2; a++)
#pragma unroll
        for (int nt = 0; nt < 8; nt++)
#pragma unroll
            for (int e = 0; e < 4; e++) acc[a][nt][e] = 0.f;

    auto issue = [&](int kc, int st) {
        char* base = sm + st * G1_STAGE_B;
        uint32_t sa = smem_u32(base);
        uint32_t sb = sa + G1_TILE_B;
#pragma unroll
        for (int it = 0; it < 4; it++) {
            int idx = tid + it * 256;
            int r = idx >> 3, cu = idx & 7;
            cp_async16(sa + (r * G1_LD + cu * 8) * 2,
                       g_cbf + (size_t)(m0 + r) * DD + kc * 64 + cu * 8);
        }
#pragma unroll
        for (int it = 0; it < 4; it++) {
            int idx = tid + it * 256;
            int r = idx >> 3, cu = idx & 7;
            cp_async16(sb + (r * G1_LD + cu * 8) * 2,
                       g_Wt + (size_t)(n0 + r) * DD + kc * 64 + cu * 8);
        }
        cp_commit();
    };

    issue(0, 0);
    issue(1, 1);

    for (int kc = 0; kc < 8; kc++) {
        // one committed group per iteration keeps wait<2> exact
        if (kc + 2 < 8) issue(kc + 2, (kc + 2) % 3); else cp_commit();
        cp_wait<2>();                   // group kc complete
        __syncthreads();
        char* base = sm + (kc % 3) * G1_STAGE_B;
        uint32_t sa = smem_u32(base);
        uint32_t sb = sa + G1_TILE_B;
#pragma unroll
        for (int ks = 0; ks < 4; ks++) {
            uint32_t af[2][4];
#pragma unroll
            for (int a = 0; a < 2; a++) {
                uint32_t addr = sa + ((wr * 32 + a * 16 + (lane & 15)) * G1_LD +
                                      ks * 16 + (lane >> 4) * 8) * 2;
                ldm_x4(af[a][0], af[a][1], af[a][2], af[a][3], addr);
            }
#pragma unroll
            for (int np = 0; np < 4; np++) {
                uint32_t b0, b1, b2, b3;
                uint32_t addr = sb + ((wc * 64 + np * 16 + ((lane >> 4) & 1) * 8 +
                                       (lane & 7)) * G1_LD +
                                      ks * 16 + ((lane >> 3) & 1) * 8) * 2;
                ldm_x4(b0, b1, b2, b3, addr);
#pragma unroll
                for (int a = 0; a < 2; a++) {
                    mma_bf16(acc[a][2 * np], af[a][0], af[a][1], af[a][2], af[a][3], b0, b1);
                    mma_bf16(acc[a][2 * np + 1], af[a][0], af[a][1], af[a][2], af[a][3], b2, b3);
                }
            }
        }
        __syncthreads();                // stage free for reuse
    }

#pragma unroll
    for (int a = 0; a < 2; a++) {
        int r0 = m0 + wr * 32 + a * 16 + g;
#pragma unroll
        for (int nt = 0; nt < 8; nt++) {
            int col = n0 + wc * 64 + nt * 8 + t4 * 2;
            float bv0 = bias[col], bv1 = bias[col + 1];
            *(__nv_bfloat162*)(g_cproj + (size_t)r0 * DD + col) =
                __floats2bfloat162_rn(acc[a][nt][0] + bv0, acc[a][nt][1] + bv1);
            *(__nv_bfloat162*)(g_cproj + (size_t)(r0 + 8) * DD + col) =
                __floats2bfloat162_rn(acc[a][nt][2] + bv0, acc[a][nt][3] + bv1);
        }
    }
}

// ---------------------------------------------------------------------------
// Fused scores + LSE - diag, diagonal-block version (R6 structure).
// Grid (49, 3): CTA = (t-pair {t0,t0+1}, s-window). 256 thr, 8 warps.
// C pair resident (M=128 x K=512, ld 520). Phase = 2 s-slots x 4 warps
// (warp tile 32x64 over M=128). Z streamed in 64-col K-chunks, 4-stage ring
// (8 slots x 9216 B); one committed cp.async group per chunk; cp_wait<2>
// gives each chunk ~3 iterations of load lead time.
// ---------------------------------------------------------------------------
#define SC_LD 520
#define SC_BYTES (128 * SC_LD * 2)       // 133120
#define SZ_LD 72
#define SZ_SLOT (64 * SZ_LD * 2)         // 9216
#define SZ_BYTES (8 * SZ_SLOT)           // 73728 (4 stages x 2 slots)
#define S_SMEM (SC_BYTES + SZ_BYTES + 64)  // 206912

__global__ __launch_bounds__(256) void k_scores() {
    extern __shared__ char sm[];
    uint32_t sC = smem_u32(sm);
    uint32_t sZ0 = sC + SC_BYTES;
    float* sRed = (float*)(sm + SC_BYTES + SZ_BYTES);

    const int t0 = blockIdx.x * 2;
    const int y = blockIdx.y;
    const int s_base = t0 + 1 + ((y == 0) ? 0 : (y == 1) ? 11 : 21);
    const int win = (y == 0) ? 11 : 10;
    const int P = (win + 1) >> 1;       // phases of 2 s (last may be 1)
    const int ITERS = 8 * P;            // 8 x 64-col K-chunks per phase

    const int tid = threadIdx.x;
    const int w = tid >> 5;
    const int lane = tid & 31;
    const int slot = w >> 2;            // s-slot within phase (0/1)
    const int wr = w & 3;               // row quarter: rows wr*32..+32 of M=128
    const int g = lane >> 2;
    const int t4 = lane & 3;

    // --- Prologue: C tiles for t0 and t0+1 (rows 0-63 / 64-127) ---
#pragma unroll
    for (int it = 0; it < 32; it++) {
        int idx = tid + it * 256;           // 0..8191 -> 128 rows x 64 uint4
        int r = idx >> 6, cu = idx & 63;
        int i = r & 63, tt = t0 + (r >> 6);
        cp_async16(sC + (r * SC_LD + cu * 8) * 2,
                   g_cproj + ((size_t)i * TT + tt) * DD + cu * 8);
    }
    // NOTE: C joins group 0 together with chunk 0 (committed inside issue_z(0))

    auto issue_z = [&](int j) {
        int p = j >> 3, ch = j & 7;
        for (int sl = 0; sl < 2; sl++) {
            if (2 * p + sl >= win) break;
            int s = s_base + 2 * p + sl;
            uint32_t dst = sZ0 + (uint32_t)((j & 3) * 2 + sl) * SZ_SLOT;
#pragma unroll
            for (int it2 = 0; it2 < 2; it2++) {
                int idx = tid + it2 * 256;  // 0..511 -> 64 rows x 8 uint4
                int rr = idx >> 3, cc = idx & 7;
                cp_async16(dst + (rr * SZ_LD + cc * 8) * 2,
                           g_zbf + ((size_t)rr * TT + s) * DD + ch * 64 + cc * 8);
            }
        }
        cp_commit();
    };

    issue_z(0);     // group 0 = C + chunk 0
    issue_z(1);     // group 1
    issue_z(2);     // group 2
    cp_wait<2>();   // group 0 (C + chunk0) complete
    __syncthreads();

    float acc[2][8][4];
#pragma unroll
    for (int a = 0; a < 2; a++)
#pragma unroll
        for (int nt = 0; nt < 8; nt++)
#pragma unroll
            for (int e = 0; e < 4; e++) acc[a][nt][e] = 0.f;

    for (int it = 0; it < ITERS; it++) {
        const int p = it >> 3, ch = it & 7;
        const bool slot_active = (2 * p + slot) < win;

        // --- Compute this 64-col K-chunk ---
        if (slot_active) {
            uint32_t sz = sZ0 + (uint32_t)((it & 3) * 2 + slot) * SZ_SLOT;
#pragma unroll
            for (int ks = 0; ks < 4; ks++) {
                uint32_t af[2][4];
#pragma unroll
                for (int a = 0; a < 2; a++) {
                    uint32_t addr = sC + ((wr * 32 + a * 16 + (lane & 15)) * SC_LD +
                                          ch * 64 + ks * 16 + (lane >> 4) * 8) * 2;
                    ldm_x4(af[a][0], af[a][1], af[a][2], af[a][3], addr);
                }
#pragma unroll
                for (int np = 0; np < 4; np++) {
                    uint32_t b0, b1, b2, b3;
                    uint32_t addr = sz + ((np * 16 + ((lane >> 4) & 1) * 8 +
                                           (lane & 7)) * SZ_LD +
                                          ks * 16 + ((lane >> 3) & 1) * 8) * 2;
                    ldm_x4(b0, b1, b2, b3, addr);
#pragma unroll
                    for (int a = 0; a < 2; a++) {
                        mma_bf16(acc[a][2 * np], af[a][0], af[a][1], af[a][2], af[a][3], b0, b1);
                        mma_bf16(acc[a][2 * np + 1], af[a][0], af[a][1], af[a][2], af[a][3], b2, b3);
                    }
                }
            }
        }
        __syncthreads();                    // stage fully consumed

        // one committed group per iteration (empty at tail keeps count exact)
        if (it + 3 < ITERS) issue_z(it + 3); else cp_commit();

        // --- End of phase: LSE - diag epilogue (overlaps in-flight loads) ---
        if (ch == 7) {
            const int s = s_base + 2 * p + slot;
            const int th = wr >> 1;         // 0 -> t0 rows, 1 -> t0+1 rows
            const int k = s - (t0 + th);
            const bool valid = slot_active && (k >= 1) && (k <= 30);

            float local = 0.f;
            if (valid) {
#pragma unroll
                for (int a = 0; a < 2; a++) {
#pragma unroll
                    for (int rp = 0; rp < 2; rp++) {
                        const int e0 = rp * 2;
                        float m = -3.4e38f;
#pragma unroll
                        for (int nt = 0; nt < 8; nt++)
                            m = fmaxf(m, fmaxf(acc[a][nt][e0], acc[a][nt][e0 + 1]));
                        m = fmaxf(m, __shfl_xor_sync(0xffffffffu, m, 1));
                        m = fmaxf(m, __shfl_xor_sync(0xffffffffu, m, 2));
                        float se = 0.f;
#pragma unroll
                        for (int nt = 0; nt < 8; nt++) {
                            se += expf((acc[a][nt][e0] - m) * INV_TEMP);
                            se += expf((acc[a][nt][e0 + 1] - m) * INV_TEMP);
                        }
                        se += __shfl_xor_sync(0xffffffffu, se, 1);
                        se += __shfl_xor_sync(0xffffffffu, se, 2);
                        float lse = m * INV_TEMP + logf(se);
                        int r = wr * 32 + a * 16 + rp * 8 + g;   // 0..127
                        int j = r & 63;                          // diag col
                        if (t4 == ((j >> 1) & 3))
                            local += lse - acc[a][j >> 3][e0 + (j & 1)] * INV_TEMP;
                    }
                }
            }
#pragma unroll
            for (int off = 16; off > 0; off >>= 1)
                local += __shfl_xor_sync(0xffffffffu, local, off);
            if (lane == 0) sRed[w] = local;
            __syncthreads();
            // sRed[w]: w = slot*4 + half*2 + {0,1}
            if (tid < 4) {
                int wsl = tid >> 1, half = tid & 1;
                if (2 * p + wsl < win) {
                    int ss = s_base + 2 * p + wsl;
                    int tt = t0 + half;
                    int kk = ss - tt;
                    if (kk >= 1 && kk <= 30)
                        g_partials[tt * HH + kk - 1] =
                            sRed[wsl * 4 + half * 2] + sRed[wsl * 4 + half * 2 + 1];
                }
            }
            // zero accumulators for next phase
#pragma unroll
            for (int a = 0; a < 2; a++)
#pragma unroll
                for (int nt = 0; nt < 8; nt++)
#pragma unroll
                    for (int e = 0; e < 4; e++) acc[a][nt][e] = 0.f;
        }

        if (it + 1 < ITERS) {
            cp_wait<2>();                   // group (it+1) complete
            __syncthreads();                // next stage visible to all warps
        }
    }
}

// ---------------------------------------------------------------------------
// Final deterministic reduction
// ---------------------------------------------------------------------------
__global__ void k_reduce(float* __restrict__ out) {
    __shared__ float sh[256];
    int tid = threadIdx.x;
    float ssum = 0.f;
    for (int i = tid; i < TM * HH; i += 256) ssum += g_partials[i];
    sh[tid] = ssum;
    __syncthreads();
    for (int off = 128; off > 0; off >>= 1) {
        if (tid < off) sh[tid] += sh[tid + off];
        __syncthreads();
    }
    if (tid == 0) out[0] = sh[0] / (float)(TM * HH * BB);
}

// ---------------------------------------------------------------------------
extern "C" void kernel_launch(void* const* d_in, const int* in_sizes, int n_in,
                              void* d_out, int out_size) {
    const float* z = (const float*)d_in[0];
    const float* c = (const float*)d_in[1];
    const float* W = (const float*)d_in[2];
    const float* bias = (const float*)d_in[3];
    float* out = (float*)d_out;
    (void)in_sizes; (void)n_in; (void)out_size;

    cudaFuncSetAttribute(k_scores, cudaFuncAttributeMaxDynamicSharedMemorySize, S_SMEM);
    cudaFuncSetAttribute(k_gemm1, cudaFuncAttributeMaxDynamicSharedMemorySize, G1_SMEM);

    __nv_bfloat16* zb = nullptr;
    __nv_bfloat16* cb = nullptr;
    cudaGetSymbolAddress((void**)&zb, g_zbf);
    cudaGetSymbolAddress((void**)&cb, g_cbf);

    k_convert<<<4096, 256>>>(z, zb);
    k_convert<<<4096, 256>>>(c, cb);
    k_convert_w<<<(DD * DD + 511) / 512, 512>>>(W);
    k_gemm1<<<dim3(64, 4), 256, G1_SMEM>>>(bias);
    k_scores<<<dim3(49, 3), 256, S_SMEM>>>();
    k_reduce<<<1, 256>>>(out);
}